// round 5
// baseline (speedup 1.0000x reference)
#include <cuda_runtime.h>
#include <cuda_bf16.h>
#include <math.h>

#define N_PROP   65536
#define N_GT     64
#define NCLS     81
#define TOTAL    512
#define MAX_POS  128
#define TPB      512
#define PPB      256            // proposals per block (2 threads each)
#define NBLK     256            // N_PROP / PPB
#define NWARP    (TPB / 32)

// -------- device scratch --------
__device__ int   g_blk_pos[NBLK];
__device__ int   g_blk_neg[NBLK];
__device__ float g_ce[TOTAL];
__device__ float g_rg[TOTAL];
__device__ int   g_count;       // barrier arrivals (reset by reducer)
__device__ int   g_done;        // ticket       (reset by reducer)

__device__ __forceinline__ float sl1(float d) {
    float ad = fabsf(d);
    return (ad < 1.0f) ? (0.5f * d * d) : (ad - 0.5f);
}

__global__ void __launch_bounds__(TPB)
k_fused(const float* __restrict__ props,
        const float* __restrict__ gts,
        const int*   __restrict__ gt_labels,
        const float* __restrict__ score,
        const float* __restrict__ txty,
        float* __restrict__ out,
        int n_gt) {
    __shared__ float4 sg[N_GT];
    __shared__ float  sga[N_GT];
    __shared__ int    slbl[N_GT];
    __shared__ float  s_ci[PPB], s_cu[PPB];
    __shared__ int    s_cj[PPB];
    __shared__ int    wpc[8], wnc[8];
    __shared__ int    swp[8], swn[8];
    __shared__ int    ssp[NBLK], ssn[NBLK];
    __shared__ int    s_numpos, s_negtot, s_offp, s_offn;
    __shared__ int    s_nent;
    __shared__ int    s_ent[TOTAL];       // packed: idx:16 | slot:9 | gt:6 | pos:1
    __shared__ int    s_last;
    __shared__ float  rc[NWARP], rr[NWARP];

    const int t    = threadIdx.x;
    const int bid  = blockIdx.x;
    const int warp = t >> 5, lane = t & 31;
    const int half = t >> 8;                 // 0: gts [0,32), 1: gts [32,64)
    const int lp   = t & (PPB - 1);          // local proposal id
    const unsigned full = 0xffffffffu;

    // ---- stage gt data ----
    if (t < N_GT) {
        float4 g = ((const float4*)gts)[t];
        sg[t] = g;
        sga[t] = (g.z - g.x) * (g.w - g.y);
        slbl[t] = gt_labels[t];
    }
    if (t == 0) s_nent = 0;
    __syncthreads();

    // ============ phase 1: IoU argmax (division-free), 2 threads/proposal ===
    const int i = bid * PPB + lp;
    const float4 p = ((const float4*)props)[i];
    const float pa = (p.z - p.x) * (p.w - p.y);

    const int j0 = half * 32;
    float bi, bu; int bj;
    {
        float4 g = sg[j0];
        float ix = fmaxf(fminf(p.z, g.z) - fmaxf(p.x, g.x), 0.0f);
        float iy = fmaxf(fminf(p.w, g.w) - fmaxf(p.y, g.y), 0.0f);
        bi = ix * iy;
        bu = ((pa + sga[j0]) - bi) + 1e-8f;   // exact reference assoc order
        bj = j0;
    }
#pragma unroll 8
    for (int j = j0 + 1; j < j0 + 32; j++) {
        float4 g = sg[j];
        float ix = fmaxf(fminf(p.z, g.z) - fmaxf(p.x, g.x), 0.0f);
        float iy = fmaxf(fminf(p.w, g.w) - fmaxf(p.y, g.y), 0.0f);
        float inter = ix * iy;
        float u = ((pa + sga[j]) - inter) + 1e-8f;
        if (inter * bu > bi * u) { bi = inter; bu = u; bj = j; }  // strict > = first argmax
    }
    if (half == 1) { s_ci[lp] = bi; s_cu[lp] = bu; s_cj[lp] = bj; }
    __syncthreads();

    int f = 0;
    unsigned bp = 0, bn = 0;
    if (half == 0) {
        float ui = s_ci[lp], uu = s_cu[lp];
        if (ui * bu > bi * uu) { bi = ui; bu = uu; bj = s_cj[lp]; }
        float miou = bi / bu;                 // single division, reference rounding
        f = (miou >= 0.5f) ? 1 : ((miou >= 0.1f) ? 2 : 0);
        bp = __ballot_sync(full, f == 1);
        bn = __ballot_sync(full, f == 2);
        if (lane == 0) { wpc[warp] = __popc(bp); wnc[warp] = __popc(bn); }
    }
    __syncthreads();
    if (t == 0) {
        int cp = 0, cn = 0;
#pragma unroll
        for (int w = 0; w < 8; w++) { cp += wpc[w]; cn += wnc[w]; }
        g_blk_pos[bid] = cp;
        g_blk_neg[bid] = cn;
    }

    // ============ global barrier (RED arrival + spin) ============
    __syncthreads();
    if (t == 0) {
        __threadfence();
        atomicAdd(&g_count, 1);              // return unused -> RED
        volatile int* vc = &g_count;
        while (*vc < NBLK) { }
        __threadfence();
    }
    __syncthreads();

    // ============ phase 2: shfl scan (256 counts) ============
    if (t < NBLK) {
        int ip  = __ldcg(&g_blk_pos[t]);
        int in_ = __ldcg(&g_blk_neg[t]);
#pragma unroll
        for (int o = 1; o < 32; o <<= 1) {
            int ap = __shfl_up_sync(full, ip, o);
            int an = __shfl_up_sync(full, in_, o);
            if (lane >= o) { ip += ap; in_ += an; }
        }
        if (lane == 31) { swp[warp] = ip; swn[warp] = in_; }
        __syncthreads();
        int basep = 0, basen = 0;
        for (int w = 0; w < warp; w++) { basep += swp[w]; basen += swn[w]; }
        ssp[t] = basep + ip;
        ssn[t] = basen + in_;
    } else {
        __syncthreads();
    }
    __syncthreads();
    if (t == 0) {
        s_offp   = (bid > 0) ? ssp[bid - 1] : 0;
        s_offn   = (bid > 0) ? ssn[bid - 1] : 0;
        s_numpos = min(ssp[NBLK - 1], MAX_POS);
        s_negtot = ssn[NBLK - 1];
    }
    __syncthreads();

    // ============ phase 2b: local slot assignment -> shared entry list ======
    const int num_pos  = s_numpos;
    const int neg_tot  = s_negtot;
    if (half == 0) {
        int pre_p = 0, pre_n = 0;
        for (int w = 0; w < warp; w++) { pre_p += wpc[w]; pre_n += wnc[w]; }
        unsigned lm = (1u << lane) - 1u;
        int neg_before = pre_n + __popc(bn & lm);
        if (f == 1) {
            int r = s_offp + pre_p + __popc(bp & lm);
            if (r < num_pos) {
                int e = i | (r << 16) | (bj << 25) | (1 << 31);
                s_ent[atomicAdd(&s_nent, 1)] = e;
            }
        } else if (f == 2) {
            int j2 = s_offn + neg_before;
            int slot = num_pos + j2;
            if (j2 < neg_tot && slot < TOTAL) {
                s_ent[atomicAdd(&s_nent, 1)] = i | (slot << 16);
            }
        }
        if (f != 2) {
            int k = (bid * PPB - s_offn) + (lp - neg_before);
            int slot = num_pos + neg_tot + k;
            if (slot < TOTAL) {
                s_ent[atomicAdd(&s_nent, 1)] = i | (slot << 16);
            }
        }
    }
    __syncthreads();

    // ============ phase 3: loss for this block's entries (warp per entry) ===
    const int nent = s_nent;
    for (int e0 = warp; e0 < nent; e0 += NWARP) {
        int e = s_ent[e0];
        int idx    = e & 0xFFFF;
        int slot   = (e >> 16) & 0x1FF;
        int g      = (e >> 25) & 0x3F;
        bool ispos = (e >> 31) & 1;
        int lbl = ispos ? slbl[g] : 0;

        const float* row = score + (size_t)idx * NCLS;
        float v0 = row[lane];
        float v1 = row[lane + 32];
        float v2 = (lane + 64 < NCLS) ? row[lane + 64] : -INFINITY;
        float m = fmaxf(fmaxf(v0, v1), v2);
#pragma unroll
        for (int o = 16; o; o >>= 1) m = fmaxf(m, __shfl_xor_sync(full, m, o));
        float s = expf(v0 - m) + expf(v1 - m) + ((lane + 64 < NCLS) ? expf(v2 - m) : 0.0f);
#pragma unroll
        for (int o = 16; o; o >>= 1) s += __shfl_xor_sync(full, s, o);

        float cand = (lbl < 32) ? v0 : ((lbl < 64) ? v1 : v2);
        float vl = __shfl_sync(full, cand, lbl & 31);

        if (lane == 0) {
            float ce = m + logf(s) - vl;
            float rg = 0.0f;
            if (ispos) {
                float4 pp = ((const float4*)props)[idx];
                float4 gb = sg[g];
                float pw = pp.z - pp.x, ph = pp.w - pp.y;
                float pcx = pp.x + 0.5f * pw, pcy = pp.y + 0.5f * ph;
                float gw = gb.z - gb.x, gh = gb.w - gb.y;
                float gcx = gb.x + 0.5f * gw, gcy = gb.y + 0.5f * gh;
                float t0 = ((gcx - pcx) / pw) * 10.0f;
                float t1 = ((gcy - pcy) / ph) * 10.0f;
                float t2 = logf(gw / pw) * 5.0f;
                float t3 = logf(gh / ph) * 5.0f;
                float4 pv = *(const float4*)(txty + ((size_t)idx * NCLS + g) * 4);
                rg = sl1(pv.x - t0) + sl1(pv.y - t1) + sl1(pv.z - t2) + sl1(pv.w - t3);
            }
            g_ce[slot] = ce;
            g_rg[slot] = rg;
        }
    }

    // ============ phase 4: last-arriving block reduces, resets state ========
    __syncthreads();
    if (t == 0) {
        __threadfence();
        s_last = (atomicAdd(&g_done, 1) == NBLK - 1) ? 1 : 0;
    }
    __syncthreads();
    if (s_last) {
        __threadfence();
        float c  = __ldcg(&g_ce[t]);
        float r2 = __ldcg(&g_rg[t]);
#pragma unroll
        for (int o = 16; o; o >>= 1) {
            c  += __shfl_xor_sync(full, c, o);
            r2 += __shfl_xor_sync(full, r2, o);
        }
        if (lane == 0) { rc[warp] = c; rr[warp] = r2; }
        __syncthreads();
        if (warp == 0) {
            float cc  = (lane < NWARP) ? rc[lane] : 0.0f;
            float rrv = (lane < NWARP) ? rr[lane] : 0.0f;
#pragma unroll
            for (int o = 8; o; o >>= 1) {
                cc  += __shfl_xor_sync(full, cc, o);
                rrv += __shfl_xor_sync(full, rrv, o);
            }
            if (lane == 0) {
                out[0] = cc  * (1.0f / (float)TOTAL);
                out[1] = rrv * (1.0f / (float)TOTAL);
                g_count = 0;                  // reset for next graph replay
                g_done  = 0;
            }
        }
    }
}

extern "C" void kernel_launch(void* const* d_in, const int* in_sizes, int n_in,
                              void* d_out, int out_size) {
    const float* props = (const float*)d_in[1];
    const float* score = (const float*)d_in[2];
    const float* txty  = (const float*)d_in[3];
    const float* gts   = (const float*)d_in[4];
    const int*   glbl  = (const int*)d_in[5];
    float* out = (float*)d_out;
    int n_gt = in_sizes[4] / 4;

    k_fused<<<NBLK, TPB>>>(props, gts, glbl, score, txty, out, n_gt);
}

// round 6
// speedup vs baseline: 1.2183x; 1.2183x over previous
#include <cuda_runtime.h>
#include <cuda_bf16.h>
#include <math.h>

#define N_PROP   65536
#define N_GT     64
#define NCLS     81
#define TOTAL    512
#define MAX_POS  128
#define TPB      512
#define PPB      256            // proposals per block (2 threads each)
#define NBLK     256            // N_PROP / PPB
#define NWARP    (TPB / 32)
#define NGRP     16             // barrier groups
#define GSZ      (NBLK / NGRP)  // 16 blocks per group
#define PAD      32             // ints per L2 line

// -------- device scratch --------
__device__ int   g_blk_pos[NBLK];
__device__ int   g_blk_neg[NBLK];
__device__ int   g_pos_list[TOTAL];   // packed (gt<<16)|i
__device__ int   g_neg_list[TOTAL];
__device__ int   g_non_list[TOTAL];
__device__ float g_ce[TOTAL];
__device__ float g_rg[TOTAL];
// hierarchical barrier state (zero-init; reset by reducer each run)
__device__ int          g_cntA[NGRP * PAD];
__device__ int          g_rootA;
__device__ volatile int g_genA;
__device__ int          g_cntB[NGRP * PAD];
__device__ int          g_rootB;
__device__ volatile int g_genB;
__device__ int          g_cntC[NGRP * PAD];
__device__ int          g_rootC;

__device__ __forceinline__ void hbar(int bid, int* cnt, int* root, volatile int* gen) {
    __syncthreads();
    if (threadIdx.x == 0) {
        __threadfence();
        int grp = bid & (NGRP - 1);
        bool released = false;
        if (atomicAdd(&cnt[grp * PAD], 1) == GSZ - 1) {
            if (atomicAdd(root, 1) == NGRP - 1) {
                __threadfence();
                *gen = 1;                 // single write-once release line
                released = true;
            }
        }
        if (!released) {
            while (*gen == 0) { }
            __threadfence();
        }
    }
    __syncthreads();
}

__device__ __forceinline__ float sl1(float d) {
    float ad = fabsf(d);
    return (ad < 1.0f) ? (0.5f * d * d) : (ad - 0.5f);
}

__global__ void __launch_bounds__(TPB)
k_fused(const float* __restrict__ props,
        const float* __restrict__ gts,
        const int*   __restrict__ gt_labels,
        const float* __restrict__ score,
        const float* __restrict__ txty,
        float* __restrict__ out,
        int n_gt) {
    __shared__ float4 sg[N_GT];
    __shared__ float  sga[N_GT];
    __shared__ int    slbl[N_GT];
    __shared__ float  s_ci[PPB], s_cu[PPB];
    __shared__ int    s_cj[PPB];
    __shared__ int    wpc[8], wnc[8];
    __shared__ int    swp[8], swn[8];
    __shared__ int    ssp[NBLK], ssn[NBLK];
    __shared__ int    s_numpos, s_negtot, s_offp, s_offn;
    __shared__ int    s_last;
    __shared__ float  rc[NWARP], rr[NWARP];

    const int t    = threadIdx.x;
    const int bid  = blockIdx.x;
    const int warp = t >> 5, lane = t & 31;
    const int half = t >> 8;                 // 0: gts [0,32), 1: gts [32,64)
    const int lp   = t & (PPB - 1);          // local proposal id
    const unsigned full = 0xffffffffu;

    // ---- stage gt data ----
    if (t < N_GT) {
        float4 g = ((const float4*)gts)[t];
        sg[t] = g;
        sga[t] = (g.z - g.x) * (g.w - g.y);
        slbl[t] = gt_labels[t];
    }
    __syncthreads();

    // ============ phase 1: IoU argmax (division-free), 2 threads/proposal ===
    const int i = bid * PPB + lp;
    const float4 p = ((const float4*)props)[i];
    const float pa = (p.z - p.x) * (p.w - p.y);

    const int j0 = half * 32;
    float bi, bu; int bj;
    {
        float4 g = sg[j0];
        float ix = fmaxf(fminf(p.z, g.z) - fmaxf(p.x, g.x), 0.0f);
        float iy = fmaxf(fminf(p.w, g.w) - fmaxf(p.y, g.y), 0.0f);
        bi = ix * iy;
        bu = ((pa + sga[j0]) - bi) + 1e-8f;   // exact reference assoc order
        bj = j0;
    }
#pragma unroll 8
    for (int j = j0 + 1; j < j0 + 32; j++) {
        float4 g = sg[j];
        float ix = fmaxf(fminf(p.z, g.z) - fmaxf(p.x, g.x), 0.0f);
        float iy = fmaxf(fminf(p.w, g.w) - fmaxf(p.y, g.y), 0.0f);
        float inter = ix * iy;
        float u = ((pa + sga[j]) - inter) + 1e-8f;
        if (inter * bu > bi * u) { bi = inter; bu = u; bj = j; }  // strict > = first argmax
    }
    if (half == 1) { s_ci[lp] = bi; s_cu[lp] = bu; s_cj[lp] = bj; }
    __syncthreads();

    int f = 0;
    unsigned bp = 0, bn = 0;
    if (half == 0) {
        float ui = s_ci[lp], uu = s_cu[lp];
        if (ui * bu > bi * uu) { bi = ui; bu = uu; bj = s_cj[lp]; }
        float miou = bi / bu;                 // single division, reference rounding
        f = (miou >= 0.5f) ? 1 : ((miou >= 0.1f) ? 2 : 0);
        bp = __ballot_sync(full, f == 1);
        bn = __ballot_sync(full, f == 2);
        if (lane == 0) { wpc[warp] = __popc(bp); wnc[warp] = __popc(bn); }
    }
    __syncthreads();
    if (t == 0) {
        int cp = 0, cn = 0;
#pragma unroll
        for (int w = 0; w < 8; w++) { cp += wpc[w]; cn += wnc[w]; }
        g_blk_pos[bid] = cp;
        g_blk_neg[bid] = cn;
    }

    hbar(bid, g_cntA, &g_rootA, &g_genA);

    // ============ phase 2: shfl scan (256 counts) ============
    if (t < NBLK) {
        int ip  = __ldcg(&g_blk_pos[t]);
        int in_ = __ldcg(&g_blk_neg[t]);
#pragma unroll
        for (int o = 1; o < 32; o <<= 1) {
            int ap = __shfl_up_sync(full, ip, o);
            int an = __shfl_up_sync(full, in_, o);
            if (lane >= o) { ip += ap; in_ += an; }
        }
        if (lane == 31) { swp[warp] = ip; swn[warp] = in_; }
        __syncthreads();
        int basep = 0, basen = 0;
        for (int w = 0; w < warp; w++) { basep += swp[w]; basen += swn[w]; }
        ssp[t] = basep + ip;
        ssn[t] = basen + in_;
    } else {
        __syncthreads();
    }
    __syncthreads();
    if (t == 0) {
        s_offp   = (bid > 0) ? ssp[bid - 1] : 0;
        s_offn   = (bid > 0) ? ssn[bid - 1] : 0;
        s_numpos = min(ssp[NBLK - 1], MAX_POS);
        s_negtot = ssn[NBLK - 1];
    }
    __syncthreads();

    // ============ phase 2b: stable select -> global lists ============
    if (half == 0) {
        int pre_p = 0, pre_n = 0;
        for (int w = 0; w < warp; w++) { pre_p += wpc[w]; pre_n += wnc[w]; }
        unsigned lm = (1u << lane) - 1u;
        int neg_before = pre_n + __popc(bn & lm);
        if (f == 1) {
            int r = s_offp + pre_p + __popc(bp & lm);
            if (r < TOTAL) g_pos_list[r] = i | (bj << 16);
        } else if (f == 2) {
            int r = s_offn + neg_before;
            if (r < TOTAL) g_neg_list[r] = i;
        }
        if (f != 2) {
            int r = (bid * PPB - s_offn) + (lp - neg_before);
            if (r < TOTAL) g_non_list[r] = i;
        }
    }

    hbar(bid, g_cntB, &g_rootB, &g_genB);

    // ============ phase 3: loss (2 warps/block -> 512 slots, balanced) ======
    if (warp < 2) {
        int slot = bid * 2 + warp;
        int num_pos = s_numpos;
        int neg_total = s_negtot;
        bool is_pos = slot < num_pos;
        int e;
        if (is_pos) e = __ldcg(&g_pos_list[slot]);
        else {
            int j = slot - num_pos;
            e = (j < neg_total) ? __ldcg(&g_neg_list[j])
                                : __ldcg(&g_non_list[j - neg_total]);
        }
        int idx = e & 0xFFFF;
        int g   = e >> 16;
        int lbl = is_pos ? slbl[g] : 0;

        const float* row = score + (size_t)idx * NCLS;
        float v0 = row[lane];
        float v1 = row[lane + 32];
        float v2 = (lane + 64 < NCLS) ? row[lane + 64] : -INFINITY;
        float m = fmaxf(fmaxf(v0, v1), v2);
#pragma unroll
        for (int o = 16; o; o >>= 1) m = fmaxf(m, __shfl_xor_sync(full, m, o));
        float s = expf(v0 - m) + expf(v1 - m) + ((lane + 64 < NCLS) ? expf(v2 - m) : 0.0f);
#pragma unroll
        for (int o = 16; o; o >>= 1) s += __shfl_xor_sync(full, s, o);

        float cand = (lbl < 32) ? v0 : ((lbl < 64) ? v1 : v2);
        float vl = __shfl_sync(full, cand, lbl & 31);

        if (lane == 0) {
            float ce = m + logf(s) - vl;
            float rg = 0.0f;
            if (is_pos) {
                float4 pp = ((const float4*)props)[idx];
                float4 gb = sg[g];
                float pw = pp.z - pp.x, ph = pp.w - pp.y;
                float pcx = pp.x + 0.5f * pw, pcy = pp.y + 0.5f * ph;
                float gw = gb.z - gb.x, gh = gb.w - gb.y;
                float gcx = gb.x + 0.5f * gw, gcy = gb.y + 0.5f * gh;
                float t0 = ((gcx - pcx) / pw) * 10.0f;
                float t1 = ((gcy - pcy) / ph) * 10.0f;
                float t2 = logf(gw / pw) * 5.0f;
                float t3 = logf(gh / ph) * 5.0f;
                float4 pv = *(const float4*)(txty + ((size_t)idx * NCLS + g) * 4);
                rg = sl1(pv.x - t0) + sl1(pv.y - t1) + sl1(pv.z - t2) + sl1(pv.w - t3);
            }
            g_ce[slot] = ce;
            g_rg[slot] = rg;
        }
    }

    // ============ phase 4: hierarchical last-arriver ticket ============
    __syncthreads();
    if (t == 0) {
        __threadfence();
        int grp = bid & (NGRP - 1);
        int win = 0;
        if (atomicAdd(&g_cntC[grp * PAD], 1) == GSZ - 1)
            if (atomicAdd(&g_rootC, 1) == NGRP - 1)
                win = 1;
        s_last = win;
    }
    __syncthreads();
    if (s_last) {
        __threadfence();
        float c  = __ldcg(&g_ce[t]);
        float r2 = __ldcg(&g_rg[t]);
#pragma unroll
        for (int o = 16; o; o >>= 1) {
            c  += __shfl_xor_sync(full, c, o);
            r2 += __shfl_xor_sync(full, r2, o);
        }
        if (lane == 0) { rc[warp] = c; rr[warp] = r2; }
        __syncthreads();
        if (warp == 0) {
            float cc  = (lane < NWARP) ? rc[lane] : 0.0f;
            float rrv = (lane < NWARP) ? rr[lane] : 0.0f;
#pragma unroll
            for (int o = 8; o; o >>= 1) {
                cc  += __shfl_xor_sync(full, cc, o);
                rrv += __shfl_xor_sync(full, rrv, o);
            }
            if (lane == 0) {
                out[0] = cc  * (1.0f / (float)TOTAL);
                out[1] = rrv * (1.0f / (float)TOTAL);
            }
        }
        // reset ALL barrier state for next graph replay (all blocks are past it)
        if (t < NGRP) {
            g_cntA[t * PAD] = 0;
            g_cntB[t * PAD] = 0;
            g_cntC[t * PAD] = 0;
        }
        if (t == 0) {
            g_rootA = 0; g_rootB = 0; g_rootC = 0;
            g_genA = 0;  g_genB = 0;
        }
    }
}

extern "C" void kernel_launch(void* const* d_in, const int* in_sizes, int n_in,
                              void* d_out, int out_size) {
    const float* props = (const float*)d_in[1];
    const float* score = (const float*)d_in[2];
    const float* txty  = (const float*)d_in[3];
    const float* gts   = (const float*)d_in[4];
    const int*   glbl  = (const int*)d_in[5];
    float* out = (float*)d_out;
    int n_gt = in_sizes[4] / 4;

    k_fused<<<NBLK, TPB>>>(props, gts, glbl, score, txty, out, n_gt);
}

// round 7
// speedup vs baseline: 1.3611x; 1.1172x over previous
#include <cuda_runtime.h>
#include <cuda_bf16.h>
#include <math.h>

#define N_PROP   65536
#define N_GT     64
#define NCLS     81
#define TOTAL    512
#define MAX_POS  128
#define TPB      512
#define PPB      256            // proposals per block (2 threads each)
#define NBLK     256            // N_PROP / PPB
#define NWARP    (TPB / 32)

// -------- device scratch --------
__device__ int   g_blk_pos[NBLK];
__device__ int   g_blk_neg[NBLK];
__device__ int   g_pos_list[TOTAL];   // packed (gt<<16)|i
__device__ int   g_neg_list[TOTAL];
__device__ int   g_non_list[TOTAL];
__device__ float g_ce[TOTAL];
__device__ float g_rg[TOTAL];
// barrier state: counters and gen flags on separate lines
__device__ int          g_cnt[2 * 32];      // [0], [32]
__device__ volatile int g_gen[2 * 32];      // [0], [32]
__device__ int          g_done;

__device__ __forceinline__ void gbar(int k) {
    __syncthreads();
    if (threadIdx.x == 0) {
        __threadfence();
        if (atomicAdd(&g_cnt[k * 32], 1) == NBLK - 1) {
            __threadfence();
            g_gen[k * 32] = 1;              // write-once release line
        } else {
            while (g_gen[k * 32] == 0) { }
            __threadfence();
        }
    }
    __syncthreads();
}

__device__ __forceinline__ float sl1(float d) {
    float ad = fabsf(d);
    return (ad < 1.0f) ? (0.5f * d * d) : (ad - 0.5f);
}

__global__ void __launch_bounds__(TPB)
k_fused(const float* __restrict__ props,
        const float* __restrict__ gts,
        const int*   __restrict__ gt_labels,
        const float* __restrict__ score,
        const float* __restrict__ txty,
        float* __restrict__ out,
        int n_gt) {
    __shared__ float4 sg[N_GT];
    __shared__ float  sga[N_GT];
    __shared__ int    slbl[N_GT];
    __shared__ float  s_ci[PPB], s_cu[PPB];
    __shared__ int    s_cj[PPB];
    __shared__ int    wpc[8], wnc[8];
    __shared__ int    swp[8], swn[8];
    __shared__ int    ssp[NBLK], ssn[NBLK];
    __shared__ int    s_numpos, s_negtot, s_offp, s_offn;
    __shared__ int    s_last;
    __shared__ float  rc[NWARP], rr[NWARP];

    const int t    = threadIdx.x;
    const int bid  = blockIdx.x;
    const int warp = t >> 5, lane = t & 31;
    const int half = t >> 8;                 // 0: gts [0,32), 1: gts [32,64)
    const int lp   = t & (PPB - 1);          // local proposal id
    const unsigned full = 0xffffffffu;

    // ---- stage gt data ----
    if (t < N_GT) {
        float4 g = ((const float4*)gts)[t];
        sg[t] = g;
        sga[t] = (g.z - g.x) * (g.w - g.y);
        slbl[t] = gt_labels[t];
    }
    __syncthreads();

    // ============ phase 1: IoU argmax, 2 indep chains per thread ============
    const int i = bid * PPB + lp;
    const float4 p = ((const float4*)props)[i];
    const float pa = (p.z - p.x) * (p.w - p.y);

    const int j0 = half * 32;
    // chain A: gts [j0, j0+16), chain B: gts [j0+16, j0+32) -- independent
    float biA, buA, biB, buB;
    int   bjA, bjB;
    {
        float4 gA = sg[j0];
        float ixA = fmaxf(fminf(p.z, gA.z) - fmaxf(p.x, gA.x), 0.0f);
        float iyA = fmaxf(fminf(p.w, gA.w) - fmaxf(p.y, gA.y), 0.0f);
        biA = ixA * iyA;
        buA = ((pa + sga[j0]) - biA) + 1e-8f;
        bjA = j0;
        float4 gB = sg[j0 + 16];
        float ixB = fmaxf(fminf(p.z, gB.z) - fmaxf(p.x, gB.x), 0.0f);
        float iyB = fmaxf(fminf(p.w, gB.w) - fmaxf(p.y, gB.y), 0.0f);
        biB = ixB * iyB;
        buB = ((pa + sga[j0 + 16]) - biB) + 1e-8f;
        bjB = j0 + 16;
    }
#pragma unroll
    for (int j = 1; j < 16; j++) {
        int jA = j0 + j, jB = j0 + 16 + j;
        float4 gA = sg[jA];
        float4 gB = sg[jB];
        float ixA = fmaxf(fminf(p.z, gA.z) - fmaxf(p.x, gA.x), 0.0f);
        float iyA = fmaxf(fminf(p.w, gA.w) - fmaxf(p.y, gA.y), 0.0f);
        float ixB = fmaxf(fminf(p.z, gB.z) - fmaxf(p.x, gB.x), 0.0f);
        float iyB = fmaxf(fminf(p.w, gB.w) - fmaxf(p.y, gB.y), 0.0f);
        float inA = ixA * iyA;
        float inB = ixB * iyB;
        float uA  = ((pa + sga[jA]) - inA) + 1e-8f;
        float uB  = ((pa + sga[jB]) - inB) + 1e-8f;
        if (inA * buA > biA * uA) { biA = inA; buA = uA; bjA = jA; }  // strict > = first argmax
        if (inB * buB > biB * uB) { biB = inB; buB = uB; bjB = jB; }
    }
    // merge chains: B has strictly higher indices -> wins only if strictly greater
    float bi = biA, bu = buA; int bj = bjA;
    if (biB * buA > biA * buB) { bi = biB; bu = buB; bj = bjB; }

    if (half == 1) { s_ci[lp] = bi; s_cu[lp] = bu; s_cj[lp] = bj; }
    __syncthreads();

    int f = 0;
    unsigned bp = 0, bn = 0;
    if (half == 0) {
        float ui = s_ci[lp], uu = s_cu[lp];
        if (ui * bu > bi * uu) { bi = ui; bu = uu; bj = s_cj[lp]; }   // upper half strictly greater
        float miou = bi / bu;                 // single division, reference rounding
        f = (miou >= 0.5f) ? 1 : ((miou >= 0.1f) ? 2 : 0);
        bp = __ballot_sync(full, f == 1);
        bn = __ballot_sync(full, f == 2);
        if (lane == 0) { wpc[warp] = __popc(bp); wnc[warp] = __popc(bn); }
    }
    __syncthreads();
    if (t == 0) {
        int cp = 0, cn = 0;
#pragma unroll
        for (int w = 0; w < 8; w++) { cp += wpc[w]; cn += wnc[w]; }
        g_blk_pos[bid] = cp;
        g_blk_neg[bid] = cn;
    }

    gbar(0);

    // ============ phase 2: shfl scan (256 counts) ============
    if (t < NBLK) {
        int ip  = __ldcg(&g_blk_pos[t]);
        int in_ = __ldcg(&g_blk_neg[t]);
#pragma unroll
        for (int o = 1; o < 32; o <<= 1) {
            int ap = __shfl_up_sync(full, ip, o);
            int an = __shfl_up_sync(full, in_, o);
            if (lane >= o) { ip += ap; in_ += an; }
        }
        if (lane == 31) { swp[warp] = ip; swn[warp] = in_; }
        __syncthreads();
        int basep = 0, basen = 0;
        for (int w = 0; w < warp; w++) { basep += swp[w]; basen += swn[w]; }
        ssp[t] = basep + ip;
        ssn[t] = basen + in_;
    } else {
        __syncthreads();
    }
    __syncthreads();
    if (t == 0) {
        s_offp   = (bid > 0) ? ssp[bid - 1] : 0;
        s_offn   = (bid > 0) ? ssn[bid - 1] : 0;
        s_numpos = min(ssp[NBLK - 1], MAX_POS);
        s_negtot = ssn[NBLK - 1];
    }
    __syncthreads();

    // ============ phase 2b: stable select -> global lists ============
    if (half == 0) {
        int pre_p = 0, pre_n = 0;
        for (int w = 0; w < warp; w++) { pre_p += wpc[w]; pre_n += wnc[w]; }
        unsigned lm = (1u << lane) - 1u;
        int neg_before = pre_n + __popc(bn & lm);
        if (f == 1) {
            int r = s_offp + pre_p + __popc(bp & lm);
            if (r < TOTAL) g_pos_list[r] = i | (bj << 16);
        } else if (f == 2) {
            int r = s_offn + neg_before;
            if (r < TOTAL) g_neg_list[r] = i;
        }
        if (f != 2) {
            int r = (bid * PPB - s_offn) + (lp - neg_before);
            if (r < TOTAL) g_non_list[r] = i;
        }
    }

    gbar(1);

    // ============ phase 3: loss (2 warps/block -> 512 slots) ============
    if (warp < 2) {
        int slot = bid * 2 + warp;
        int num_pos = s_numpos;
        int neg_total = s_negtot;
        bool is_pos = slot < num_pos;
        int e;
        if (is_pos) e = __ldcg(&g_pos_list[slot]);
        else {
            int j = slot - num_pos;
            e = (j < neg_total) ? __ldcg(&g_neg_list[j])
                                : __ldcg(&g_non_list[j - neg_total]);
        }
        int idx = e & 0xFFFF;
        int g   = e >> 16;
        int lbl = is_pos ? slbl[g] : 0;

        const float* row = score + (size_t)idx * NCLS;
        float v0 = row[lane];
        float v1 = row[lane + 32];
        float v2 = (lane + 64 < NCLS) ? row[lane + 64] : -INFINITY;
        float m = fmaxf(fmaxf(v0, v1), v2);
#pragma unroll
        for (int o = 16; o; o >>= 1) m = fmaxf(m, __shfl_xor_sync(full, m, o));
        float s = expf(v0 - m) + expf(v1 - m) + ((lane + 64 < NCLS) ? expf(v2 - m) : 0.0f);
#pragma unroll
        for (int o = 16; o; o >>= 1) s += __shfl_xor_sync(full, s, o);

        float cand = (lbl < 32) ? v0 : ((lbl < 64) ? v1 : v2);
        float vl = __shfl_sync(full, cand, lbl & 31);

        if (lane == 0) {
            float ce = m + logf(s) - vl;
            float rg = 0.0f;
            if (is_pos) {
                float4 pp = ((const float4*)props)[idx];
                float4 gb = sg[g];
                float pw = pp.z - pp.x, ph = pp.w - pp.y;
                float pcx = pp.x + 0.5f * pw, pcy = pp.y + 0.5f * ph;
                float gw = gb.z - gb.x, gh = gb.w - gb.y;
                float gcx = gb.x + 0.5f * gw, gcy = gb.y + 0.5f * gh;
                float t0 = ((gcx - pcx) / pw) * 10.0f;
                float t1 = ((gcy - pcy) / ph) * 10.0f;
                float t2 = logf(gw / pw) * 5.0f;
                float t3 = logf(gh / ph) * 5.0f;
                float4 pv = *(const float4*)(txty + ((size_t)idx * NCLS + g) * 4);
                rg = sl1(pv.x - t0) + sl1(pv.y - t1) + sl1(pv.z - t2) + sl1(pv.w - t3);
            }
            g_ce[slot] = ce;
            g_rg[slot] = rg;
        }
    }

    // ============ phase 4: last-arriving block reduces, resets state ========
    __syncthreads();
    if (t == 0) {
        __threadfence();
        s_last = (atomicAdd(&g_done, 1) == NBLK - 1) ? 1 : 0;
    }
    __syncthreads();
    if (s_last) {
        __threadfence();
        float c  = __ldcg(&g_ce[t]);
        float r2 = __ldcg(&g_rg[t]);
#pragma unroll
        for (int o = 16; o; o >>= 1) {
            c  += __shfl_xor_sync(full, c, o);
            r2 += __shfl_xor_sync(full, r2, o);
        }
        if (lane == 0) { rc[warp] = c; rr[warp] = r2; }
        __syncthreads();
        if (warp == 0) {
            float cc  = (lane < NWARP) ? rc[lane] : 0.0f;
            float rrv = (lane < NWARP) ? rr[lane] : 0.0f;
#pragma unroll
            for (int o = 8; o; o >>= 1) {
                cc  += __shfl_xor_sync(full, cc, o);
                rrv += __shfl_xor_sync(full, rrv, o);
            }
            if (lane == 0) {
                out[0] = cc  * (1.0f / (float)TOTAL);
                out[1] = rrv * (1.0f / (float)TOTAL);
            }
        }
        // reset barrier state for next graph replay (all blocks are past it)
        if (t == 0) {
            g_cnt[0] = 0; g_cnt[32] = 0;
            g_gen[0] = 0; g_gen[32] = 0;
            g_done   = 0;
        }
    }
}

extern "C" void kernel_launch(void* const* d_in, const int* in_sizes, int n_in,
                              void* d_out, int out_size) {
    const float* props = (const float*)d_in[1];
    const float* score = (const float*)d_in[2];
    const float* txty  = (const float*)d_in[3];
    const float* gts   = (const float*)d_in[4];
    const int*   glbl  = (const int*)d_in[5];
    float* out = (float*)d_out;
    int n_gt = in_sizes[4] / 4;

    k_fused<<<NBLK, TPB>>>(props, gts, glbl, score, txty, out, n_gt);
}